// round 7
// baseline (speedup 1.0000x reference)
#include <cuda_runtime.h>
#include <math.h>

// ---------------------------------------------------------------------------
// Projection_12438225290005: tube-of-response projection, 3 axis frames.
//
// R6: warp-per-LOR. R5 (block-per-LOR) ran at ~27% of the issue floor:
// 128-thread CTAs with one slice per thread -> no ILP, shuffle+smem+2 bars per
// 128 slices. Now one warp owns a LOR; each lane owns 4 slices (kz = lane+32j)
// with 4 independent accumulator chains, and the reduction is 5 shuffles.
// Taps are fully branchless: w = max(0, 1 - sqrt(d2)/kw), unconditional load
// (interior geometry guarantees in-bounds; w=0 reproduces the reference's
// window/inbounds masking exactly given corners are statically pruned).
//
//   - prep kernel: per-LOR linear coefficients fx(kz)=Ax+Bx*kz, fy(kz)=Ay+By*kz
//   - G=128 compile-time strides; g_imgT selected device-side via TPOSE bool
//   - (+-2,+-2) corners provably zero (min d2=4.5 > 9/pi) -> pruned
// ---------------------------------------------------------------------------

#define G 128
#define GSQ (G * G)
#define MAX_LORS (1 << 20)
#define WARPS_PER_BLOCK 8

__device__ float  g_imgT[G * G * G];          // transposed image for px frame
__device__ float4 g_prm[3][MAX_LORS];         // Ax, Bx, Ay, By
__device__ float  g_stp[3][MAX_LORS];         // step

// g_imgT[a][c][b] = in[a][b][c]
__global__ void transpose_bc_kernel(const float* __restrict__ in) {
    __shared__ float tile[32][33];
    const int a  = blockIdx.z;
    const int b0 = blockIdx.y * 32;
    const int c0 = blockIdx.x * 32;
    const float* src = in     + (size_t)a * GSQ;
    float*       dst = g_imgT + (size_t)a * GSQ;
#pragma unroll
    for (int i = threadIdx.y; i < 32; i += 8)
        tile[i][threadIdx.x] = src[(b0 + i) * G + c0 + threadIdx.x];
    __syncthreads();
#pragma unroll
    for (int i = threadIdx.y; i < 32; i += 8)
        dst[(c0 + i) * G + b0 + threadIdx.x] = tile[threadIdx.x][i];
}

// One thread per LOR. P0/P1/P2 permute grid/center/size ONLY (lors are
// already frame-local — verified by the passing R5).
template <int P0, int P1, int P2>
__global__ void prep_kernel(const int*   __restrict__ grid,
                            const float* __restrict__ center,
                            const float* __restrict__ size,
                            const float* __restrict__ lors,
                            int n, int set)
{
    int i = blockIdx.x * blockDim.x + threadIdx.x;
    if (i >= n) return;
    const float sz0 = size[P0], sz1 = size[P1], sz2 = size[P2];
    const int   n0 = grid[P0], n1 = grid[P1], n2 = grid[P2];
    const float vs0 = sz0 / (float)n0;
    const float vs1 = sz1 / (float)n1;
    const float vs2 = sz2 / (float)n2;
    const float lo0 = center[P0] - 0.5f * sz0;
    const float lo1 = center[P1] - 0.5f * sz1;
    const float lo2 = center[P2] - 0.5f * sz2;

    const float* L = lors + (size_t)i * 6;
    const float p10 = L[0], p11 = L[1], p12 = L[2];
    const float d0  = L[3] - p10;
    const float d1  = L[4] - p11;
    const float d2c = L[5] - p12;
    const float len = sqrtf(d0 * d0 + d1 * d1 + d2c * d2c);
    const float inv_dz = 1.0f / d2c;
    const float t0 = (lo2 + 0.5f * vs2 - p12) * inv_dz;   // t(kz)=t0+kz*dt
    const float dt = vs2 * inv_dz;
    const float Ax = (p10 + t0 * d0 - lo0) / vs0 - 0.5f;
    const float Bx = dt * d0 / vs0;
    const float Ay = (p11 + t0 * d1 - lo1) / vs1 - 0.5f;
    const float By = dt * d1 / vs1;
    g_prm[set][i] = make_float4(Ax, Bx, Ay, By);
    g_stp[set][i] = vs2 * len / fabsf(d2c);
}

// Hot kernel: one WARP per LOR; lane handles kz = lane + 32j, j=0..3.
template <int S0, int S1, bool TPOSE>
__global__ __launch_bounds__(32 * WARPS_PER_BLOCK)
void tor_fast_kernel(const float* __restrict__ img_in, int set,
                     float* __restrict__ out, int n_lors)
{
    const float* img = TPOSE ? (const float*)g_imgT : img_in;

    const int warp = threadIdx.x >> 5;
    const int lane = threadIdx.x & 31;
    const int lor  = blockIdx.x * WARPS_PER_BLOCK + warp;
    if (lor >= n_lors) return;

    const float4 P = __ldg(&g_prm[set][lor]);

    const float KW2    = 2.8647889756541160f;   // 9/pi
    const float INV_KW = 0.59081795026046127f;  // 1/sqrt(9/pi)

    float acc = 0.0f;

#pragma unroll
    for (int j = 0; j < 4; ++j) {
        const int   kz  = lane + 32 * j;
        const float kzf = (float)kz;
        const float fx = fmaf(kzf, P.y, P.x);
        const float fy = fmaf(kzf, P.w, P.z);
        const int ix = __float2int_rn(fx);   // half-to-even == jnp.round
        const int iy = __float2int_rn(fy);

        const float ux = (float)ix - fx;     // in [-0.5, 0.5]
        const float uy = (float)iy - fy;
        float xs[5], ys[5];
#pragma unroll
        for (int o = 0; o < 5; ++o) {
            const float a = ux + (float)(o - 2);
            const float b = uy + (float)(o - 2);
            xs[o] = a * a;
            ys[o] = b * b;
        }

        if ((unsigned)(ix - 2) <= (unsigned)(G - 5) &&
            (unsigned)(iy - 2) <= (unsigned)(G - 5)) {
            // interior (always true for this dataset): branchless 17 taps,
            // unconditional loads, w clamps to zero beyond the kernel radius.
            const float* p = img + ix * S0 + iy * S1 + kz;
#pragma unroll
            for (int o0 = -2; o0 <= 2; ++o0) {
#pragma unroll
                for (int o1 = -2; o1 <= 2; ++o1) {
                    if (o0 * o0 + o1 * o1 == 8) continue;   // corners: w==0 always
                    const float d2 = xs[o0 + 2] + ys[o1 + 2];
                    const float w  = fmaxf(0.0f, fmaf(-sqrtf(d2), INV_KW, 1.0f));
                    acc = fmaf(w, __ldg(p + (o0 * S0 + o1 * S1)), acc);
                }
            }
        } else {
            // edge fallback (kept for generality): per-tap bounds
#pragma unroll
            for (int o0 = -2; o0 <= 2; ++o0) {
#pragma unroll
                for (int o1 = -2; o1 <= 2; ++o1) {
                    if (o0 * o0 + o1 * o1 == 8) continue;
                    const int jx = ix + o0;
                    const int jy = iy + o1;
                    const float d2 = xs[o0 + 2] + ys[o1 + 2];
                    if (d2 < KW2 && (unsigned)jx < (unsigned)G && (unsigned)jy < (unsigned)G) {
                        const float w = fmaxf(0.0f, fmaf(-sqrtf(d2), INV_KW, 1.0f));
                        acc = fmaf(w, __ldg(img + jx * S0 + jy * S1 + kz), acc);
                    }
                }
            }
        }
    }

    // warp reduction
#pragma unroll
    for (int sft = 16; sft > 0; sft >>= 1)
        acc += __shfl_down_sync(0xFFFFFFFFu, acc, sft);
    if (lane == 0)
        out[lor] = acc * __ldg(&g_stp[set][lor]);
}

// ------------------------ generic fallback (R2 path, passed) ----------------
template <int P0, int P1, int P2>
__global__ __launch_bounds__(128)
void tor_generic_kernel(const float* __restrict__ img_in,
                        const int*   __restrict__ grid,
                        const float* __restrict__ center,
                        const float* __restrict__ size,
                        const float* __restrict__ lors,
                        float*       __restrict__ out,
                        int n_lors)
{
    const int lor = blockIdx.x;
    if (lor >= n_lors) return;
    const int g0 = grid[0], g1 = grid[1], g2 = grid[2];
    const int gs[3]   = { g0, g1, g2 };
    const int istr[3] = { g1 * g2, g2, 1 };
    const int n0 = gs[P0], n1 = gs[P1], n2 = gs[P2];
    const int s0 = istr[P0], s1 = istr[P1], s2 = istr[P2];
    const float* img = img_in;

    const float sz0 = size[P0], sz1 = size[P1], sz2 = size[P2];
    const float vs0 = sz0 / (float)n0, vs1 = sz1 / (float)n1, vs2 = sz2 / (float)n2;
    const float lo0 = center[P0] - sz0 * 0.5f;
    const float lo1 = center[P1] - sz1 * 0.5f;
    const float lo2 = center[P2] - sz2 * 0.5f;

    const float* L = lors + (size_t)lor * 6;
    const float p1x = __ldg(L + 0), p1y = __ldg(L + 1), p1z = __ldg(L + 2);
    const float dx = __ldg(L + 3) - p1x, dy = __ldg(L + 4) - p1y, dz = __ldg(L + 5) - p1z;
    const float len = sqrtf(dx * dx + dy * dy + dz * dz);
    const float step = vs2 * len / fabsf(dz);
    const float inv_dz = 1.0f / dz, inv_vs0 = 1.0f / vs0, inv_vs1 = 1.0f / vs1;
    const float KW2 = 2.8647889756541160f, INV_KW = 0.59081795026046127f;

    float acc = 0.0f;
    for (int kz = threadIdx.x; kz < n2; kz += blockDim.x) {
        const float zc = lo2 + ((float)kz + 0.5f) * vs2;
        const float t  = (zc - p1z) * inv_dz;
        const float fx = (fmaf(t, dx, p1x) - lo0) * inv_vs0 - 0.5f;
        const float fy = (fmaf(t, dy, p1y) - lo1) * inv_vs1 - 0.5f;
        const int ix = __float2int_rn(fx);
        const int iy = __float2int_rn(fy);
#pragma unroll
        for (int o0 = -2; o0 <= 2; ++o0) {
#pragma unroll
            for (int o1 = -2; o1 <= 2; ++o1) {
                if (o0 * o0 + o1 * o1 == 8) continue;
                const int jx = ix + o0, jy = iy + o1;
                const float ddx = (float)jx - fx, ddy = (float)jy - fy;
                const float d2 = ddx * ddx + ddy * ddy;
                if (d2 < KW2 && (unsigned)jx < (unsigned)n0 && (unsigned)jy < (unsigned)n1) {
                    const float w = fmaxf(0.0f, fmaf(-sqrtf(d2), INV_KW, 1.0f));
                    acc = fmaf(w, __ldg(&img[jx * s0 + jy * s1 + kz * s2]), acc);
                }
            }
        }
    }
#pragma unroll
    for (int sft = 16; sft > 0; sft >>= 1)
        acc += __shfl_down_sync(0xFFFFFFFFu, acc, sft);
    __shared__ float wsum[4];
    if ((threadIdx.x & 31) == 0) wsum[threadIdx.x >> 5] = acc;
    __syncthreads();
    if (threadIdx.x == 0)
        out[lor] = (wsum[0] + wsum[1] + wsum[2] + wsum[3]) * step;
}

extern "C" void kernel_launch(void* const* d_in, const int* in_sizes, int n_in,
                              void* d_out, int out_size)
{
    const float* image  = (const float*)d_in[0];
    const int*   grid   = (const int*)  d_in[1];
    const float* center = (const float*)d_in[2];
    const float* size   = (const float*)d_in[3];
    const float* xlors  = (const float*)d_in[4];
    const float* ylors  = (const float*)d_in[5];
    const float* zlors  = (const float*)d_in[6];
    float* out = (float*)d_out;

    const int nx = in_sizes[4] / 6;
    const int ny = in_sizes[5] / 6;
    const int nz = in_sizes[6] / 6;

    const long long nimg = in_sizes[0];
    const bool fast = (nimg == (long long)G * G * G) &&
                      nx <= MAX_LORS && ny <= MAX_LORS && nz <= MAX_LORS;

    if (fast) {
        {   // transpose for px frame (walked image axis must be stride-1)
            dim3 tb(32, 8), tg(G / 32, G / 32, G);
            transpose_bc_kernel<<<tg, tb>>>(image);
        }
        const int PT = 256;
        if (nx > 0) prep_kernel<2, 0, 1><<<(nx + PT - 1) / PT, PT>>>(grid, center, size, xlors, nx, 0);
        if (ny > 0) prep_kernel<1, 0, 2><<<(ny + PT - 1) / PT, PT>>>(grid, center, size, ylors, ny, 1);
        if (nz > 0) prep_kernel<0, 1, 2><<<(nz + PT - 1) / PT, PT>>>(grid, center, size, zlors, nz, 2);

        const int W = WARPS_PER_BLOCK;
        // px: image[jy][kz][jx] = g_imgT[jy][jx][kz] -> S0=G, S1=GSQ (TPOSE)
        if (nx > 0) tor_fast_kernel<G,   GSQ, true ><<<(nx + W - 1) / W, 32 * W>>>(image, 0, out, nx);
        // py: image[jy][jx][kz] -> S0=G, S1=GSQ
        if (ny > 0) tor_fast_kernel<G,   GSQ, false><<<(ny + W - 1) / W, 32 * W>>>(image, 1, out + nx, ny);
        // pz: image[jx][jy][kz] -> S0=GSQ, S1=G
        if (nz > 0) tor_fast_kernel<GSQ, G,   false><<<(nz + W - 1) / W, 32 * W>>>(image, 2, out + nx + ny, nz);
    } else {
        if (nx > 0) tor_generic_kernel<2, 0, 1><<<nx, 128>>>(image, grid, center, size, xlors, out, nx);
        if (ny > 0) tor_generic_kernel<1, 0, 2><<<ny, 128>>>(image, grid, center, size, ylors, out + nx, ny);
        if (nz > 0) tor_generic_kernel<0, 1, 2><<<nz, 128>>>(image, grid, center, size, zlors, out + nx + ny, nz);
    }
}

// round 8
// speedup vs baseline: 1.5680x; 1.5680x over previous
#include <cuda_runtime.h>
#include <math.h>

// ---------------------------------------------------------------------------
// Projection_12438225290005: tube-of-response projection, 3 axis frames.
//
// R7: hot kernel is L1tex-WAVEFRONT bound (per-warp row drift ~16 runs/LDG).
// So: warp-per-LOR ILP (R6 structure) + CONDITIONAL taps (R5 load count).
//   - 5 cross taps (o0^2+o1^2<=1): always pass d2<kw^2 (max 2.5<2.865) ->
//     unconditional load, no test, no clamp (w>0 guaranteed)
//   - 12 ring taps: test d2<KW2, and only then sqrt+load+fma (w>0 inside)
//   - (+-2,+-2) corners: min d2=4.5 -> statically pruned
//   - w>0 implies |ddx|,|ddy| < 1.693 < 2.5 -> tap automatically inside the
//     reference's 5x5 window, so the test reproduces window+max(0,.) exactly
//   - prep kernel folds all per-LOR setup into fx(kz)=Ax+Bx*kz etc.
//   - g_imgT (device-side selected!) gives stride-1 walks for all frames
// ---------------------------------------------------------------------------

#define G 128
#define GSQ (G * G)
#define MAX_LORS (1 << 20)
#define WARPS_PER_BLOCK 8

__device__ float  g_imgT[G * G * G];          // transposed image for px frame
__device__ float4 g_prm[3][MAX_LORS];         // Ax, Bx, Ay, By
__device__ float  g_stp[3][MAX_LORS];         // step

// g_imgT[a][c][b] = in[a][b][c]
__global__ void transpose_bc_kernel(const float* __restrict__ in) {
    __shared__ float tile[32][33];
    const int a  = blockIdx.z;
    const int b0 = blockIdx.y * 32;
    const int c0 = blockIdx.x * 32;
    const float* src = in     + (size_t)a * GSQ;
    float*       dst = g_imgT + (size_t)a * GSQ;
#pragma unroll
    for (int i = threadIdx.y; i < 32; i += 8)
        tile[i][threadIdx.x] = src[(b0 + i) * G + c0 + threadIdx.x];
    __syncthreads();
#pragma unroll
    for (int i = threadIdx.y; i < 32; i += 8)
        dst[(c0 + i) * G + b0 + threadIdx.x] = tile[threadIdx.x][i];
}

// One thread per LOR. P0/P1/P2 permute grid/center/size ONLY (lors are
// already frame-local — verified by passing R5/R6).
template <int P0, int P1, int P2>
__global__ void prep_kernel(const int*   __restrict__ grid,
                            const float* __restrict__ center,
                            const float* __restrict__ size,
                            const float* __restrict__ lors,
                            int n, int set)
{
    int i = blockIdx.x * blockDim.x + threadIdx.x;
    if (i >= n) return;
    const float sz0 = size[P0], sz1 = size[P1], sz2 = size[P2];
    const int   n0 = grid[P0], n1 = grid[P1], n2 = grid[P2];
    const float vs0 = sz0 / (float)n0;
    const float vs1 = sz1 / (float)n1;
    const float vs2 = sz2 / (float)n2;
    const float lo0 = center[P0] - 0.5f * sz0;
    const float lo1 = center[P1] - 0.5f * sz1;
    const float lo2 = center[P2] - 0.5f * sz2;

    const float* L = lors + (size_t)i * 6;
    const float p10 = L[0], p11 = L[1], p12 = L[2];
    const float d0  = L[3] - p10;
    const float d1  = L[4] - p11;
    const float d2c = L[5] - p12;
    const float len = sqrtf(d0 * d0 + d1 * d1 + d2c * d2c);
    const float inv_dz = 1.0f / d2c;
    const float t0 = (lo2 + 0.5f * vs2 - p12) * inv_dz;   // t(kz)=t0+kz*dt
    const float dt = vs2 * inv_dz;
    const float Ax = (p10 + t0 * d0 - lo0) / vs0 - 0.5f;
    const float Bx = dt * d0 / vs0;
    const float Ay = (p11 + t0 * d1 - lo1) / vs1 - 0.5f;
    const float By = dt * d1 / vs1;
    g_prm[set][i] = make_float4(Ax, Bx, Ay, By);
    g_stp[set][i] = vs2 * len / fabsf(d2c);
}

// Hot kernel: one WARP per LOR; lane handles kz = lane + 32j, j=0..3.
template <int S0, int S1, bool TPOSE>
__global__ __launch_bounds__(32 * WARPS_PER_BLOCK)
void tor_fast_kernel(const float* __restrict__ img_in, int set,
                     float* __restrict__ out, int n_lors)
{
    const float* img = TPOSE ? (const float*)g_imgT : img_in;

    const int warp = threadIdx.x >> 5;
    const int lane = threadIdx.x & 31;
    const int lor  = blockIdx.x * WARPS_PER_BLOCK + warp;
    if (lor >= n_lors) return;

    const float4 P = __ldg(&g_prm[set][lor]);

    const float KW2    = 2.8647889756541160f;   // 9/pi
    const float INV_KW = 0.59081795026046127f;  // 1/sqrt(9/pi)

    float acc = 0.0f;

#pragma unroll
    for (int j = 0; j < 4; ++j) {
        const int   kz  = lane + 32 * j;
        const float kzf = (float)kz;
        const float fx = fmaf(kzf, P.y, P.x);
        const float fy = fmaf(kzf, P.w, P.z);
        const int ix = __float2int_rn(fx);   // half-to-even == jnp.round
        const int iy = __float2int_rn(fy);

        const float ux = (float)ix - fx;     // in [-0.5, 0.5]
        const float uy = (float)iy - fy;
        float xs[5], ys[5];
#pragma unroll
        for (int o = 0; o < 5; ++o) {
            const float a = ux + (float)(o - 2);
            const float b = uy + (float)(o - 2);
            xs[o] = a * a;
            ys[o] = b * b;
        }

        if ((unsigned)(ix - 2) <= (unsigned)(G - 5) &&
            (unsigned)(iy - 2) <= (unsigned)(G - 5)) {
            const float* p = img + ix * S0 + iy * S1 + kz;
#pragma unroll
            for (int o0 = -2; o0 <= 2; ++o0) {
#pragma unroll
                for (int o1 = -2; o1 <= 2; ++o1) {
                    const int r2 = o0 * o0 + o1 * o1;
                    if (r2 == 8) continue;               // corners: never pass
                    const float d2 = xs[o0 + 2] + ys[o1 + 2];
                    if (r2 <= 1) {
                        // cross taps: always pass, w>0 guaranteed
                        const float w = fmaf(-sqrtf(d2), INV_KW, 1.0f);
                        acc = fmaf(w, __ldg(p + (o0 * S0 + o1 * S1)), acc);
                    } else if (d2 < KW2) {
                        // ring taps: load only when weight positive
                        const float w = fmaf(-sqrtf(d2), INV_KW, 1.0f);
                        acc = fmaf(w, __ldg(p + (o0 * S0 + o1 * S1)), acc);
                    }
                }
            }
        } else {
            // edge fallback (not hit for this dataset): per-tap bounds
#pragma unroll
            for (int o0 = -2; o0 <= 2; ++o0) {
#pragma unroll
                for (int o1 = -2; o1 <= 2; ++o1) {
                    if (o0 * o0 + o1 * o1 == 8) continue;
                    const int jx = ix + o0;
                    const int jy = iy + o1;
                    const float d2 = xs[o0 + 2] + ys[o1 + 2];
                    if (d2 < KW2 && (unsigned)jx < (unsigned)G && (unsigned)jy < (unsigned)G) {
                        const float w = fmaf(-sqrtf(d2), INV_KW, 1.0f);
                        acc = fmaf(w, __ldg(img + jx * S0 + jy * S1 + kz), acc);
                    }
                }
            }
        }
    }

    // warp reduction
#pragma unroll
    for (int sft = 16; sft > 0; sft >>= 1)
        acc += __shfl_down_sync(0xFFFFFFFFu, acc, sft);
    if (lane == 0)
        out[lor] = acc * __ldg(&g_stp[set][lor]);
}

// ------------------------ generic fallback (R2 path, passed) ----------------
template <int P0, int P1, int P2>
__global__ __launch_bounds__(128)
void tor_generic_kernel(const float* __restrict__ img_in,
                        const int*   __restrict__ grid,
                        const float* __restrict__ center,
                        const float* __restrict__ size,
                        const float* __restrict__ lors,
                        float*       __restrict__ out,
                        int n_lors)
{
    const int lor = blockIdx.x;
    if (lor >= n_lors) return;
    const int g0 = grid[0], g1 = grid[1], g2 = grid[2];
    const int gs[3]   = { g0, g1, g2 };
    const int istr[3] = { g1 * g2, g2, 1 };
    const int n0 = gs[P0], n1 = gs[P1], n2 = gs[P2];
    const int s0 = istr[P0], s1 = istr[P1], s2 = istr[P2];
    const float* img = img_in;

    const float sz0 = size[P0], sz1 = size[P1], sz2 = size[P2];
    const float vs0 = sz0 / (float)n0, vs1 = sz1 / (float)n1, vs2 = sz2 / (float)n2;
    const float lo0 = center[P0] - sz0 * 0.5f;
    const float lo1 = center[P1] - sz1 * 0.5f;
    const float lo2 = center[P2] - sz2 * 0.5f;

    const float* L = lors + (size_t)lor * 6;
    const float p1x = __ldg(L + 0), p1y = __ldg(L + 1), p1z = __ldg(L + 2);
    const float dx = __ldg(L + 3) - p1x, dy = __ldg(L + 4) - p1y, dz = __ldg(L + 5) - p1z;
    const float len = sqrtf(dx * dx + dy * dy + dz * dz);
    const float step = vs2 * len / fabsf(dz);
    const float inv_dz = 1.0f / dz, inv_vs0 = 1.0f / vs0, inv_vs1 = 1.0f / vs1;
    const float KW2 = 2.8647889756541160f, INV_KW = 0.59081795026046127f;

    float acc = 0.0f;
    for (int kz = threadIdx.x; kz < n2; kz += blockDim.x) {
        const float zc = lo2 + ((float)kz + 0.5f) * vs2;
        const float t  = (zc - p1z) * inv_dz;
        const float fx = (fmaf(t, dx, p1x) - lo0) * inv_vs0 - 0.5f;
        const float fy = (fmaf(t, dy, p1y) - lo1) * inv_vs1 - 0.5f;
        const int ix = __float2int_rn(fx);
        const int iy = __float2int_rn(fy);
#pragma unroll
        for (int o0 = -2; o0 <= 2; ++o0) {
#pragma unroll
            for (int o1 = -2; o1 <= 2; ++o1) {
                if (o0 * o0 + o1 * o1 == 8) continue;
                const int jx = ix + o0, jy = iy + o1;
                const float ddx = (float)jx - fx, ddy = (float)jy - fy;
                const float d2 = ddx * ddx + ddy * ddy;
                if (d2 < KW2 && (unsigned)jx < (unsigned)n0 && (unsigned)jy < (unsigned)n1) {
                    const float w = fmaf(-sqrtf(d2), INV_KW, 1.0f);
                    acc = fmaf(w, __ldg(&img[jx * s0 + jy * s1 + kz * s2]), acc);
                }
            }
        }
    }
#pragma unroll
    for (int sft = 16; sft > 0; sft >>= 1)
        acc += __shfl_down_sync(0xFFFFFFFFu, acc, sft);
    __shared__ float wsum[4];
    if ((threadIdx.x & 31) == 0) wsum[threadIdx.x >> 5] = acc;
    __syncthreads();
    if (threadIdx.x == 0)
        out[lor] = (wsum[0] + wsum[1] + wsum[2] + wsum[3]) * step;
}

extern "C" void kernel_launch(void* const* d_in, const int* in_sizes, int n_in,
                              void* d_out, int out_size)
{
    const float* image  = (const float*)d_in[0];
    const int*   grid   = (const int*)  d_in[1];
    const float* center = (const float*)d_in[2];
    const float* size   = (const float*)d_in[3];
    const float* xlors  = (const float*)d_in[4];
    const float* ylors  = (const float*)d_in[5];
    const float* zlors  = (const float*)d_in[6];
    float* out = (float*)d_out;

    const int nx = in_sizes[4] / 6;
    const int ny = in_sizes[5] / 6;
    const int nz = in_sizes[6] / 6;

    const long long nimg = in_sizes[0];
    const bool fast = (nimg == (long long)G * G * G) &&
                      nx <= MAX_LORS && ny <= MAX_LORS && nz <= MAX_LORS;

    if (fast) {
        {   // transpose for px frame (walked image axis must be stride-1)
            dim3 tb(32, 8), tg(G / 32, G / 32, G);
            transpose_bc_kernel<<<tg, tb>>>(image);
        }
        const int PT = 256;
        if (nx > 0) prep_kernel<2, 0, 1><<<(nx + PT - 1) / PT, PT>>>(grid, center, size, xlors, nx, 0);
        if (ny > 0) prep_kernel<1, 0, 2><<<(ny + PT - 1) / PT, PT>>>(grid, center, size, ylors, ny, 1);
        if (nz > 0) prep_kernel<0, 1, 2><<<(nz + PT - 1) / PT, PT>>>(grid, center, size, zlors, nz, 2);

        const int W = WARPS_PER_BLOCK;
        // px: image[jy][kz][jx] = g_imgT[jy][jx][kz] -> S0=G, S1=GSQ (TPOSE)
        if (nx > 0) tor_fast_kernel<G,   GSQ, true ><<<(nx + W - 1) / W, 32 * W>>>(image, 0, out, nx);
        // py: image[jy][jx][kz] -> S0=G, S1=GSQ
        if (ny > 0) tor_fast_kernel<G,   GSQ, false><<<(ny + W - 1) / W, 32 * W>>>(image, 1, out + nx, ny);
        // pz: image[jx][jy][kz] -> S0=GSQ, S1=G
        if (nz > 0) tor_fast_kernel<GSQ, G,   false><<<(nz + W - 1) / W, 32 * W>>>(image, 2, out + nx + ny, nz);
    } else {
        if (nx > 0) tor_generic_kernel<2, 0, 1><<<nx, 128>>>(image, grid, center, size, xlors, out, nx);
        if (ny > 0) tor_generic_kernel<1, 0, 2><<<ny, 128>>>(image, grid, center, size, ylors, out + nx, ny);
        if (nz > 0) tor_generic_kernel<0, 1, 2><<<nz, 128>>>(image, grid, center, size, zlors, out + nx + ny, nz);
    }
}

// round 9
// speedup vs baseline: 2.4397x; 1.5560x over previous
#include <cuda_runtime.h>
#include <math.h>

// ---------------------------------------------------------------------------
// Projection_12438225290005: tube-of-response projection, 3 axis frames.
//
// R8 = R7 (warp-per-LOR, conditional ring taps — best passing structure) with
// one surgical change: sqrtf(d2) -> d2 * rsqrtf(max(d2,1e-30)).
// Without fast-math, sqrtf lowers to an IEEE multi-instruction sequence that
// issues (under predication) for every tap; MUFU.RSQ+FMUL is 2 instructions
// with ~2^-22 rel error (weight abs err <= 1e-6, tolerance 1e-3; d2=0 -> 0).
//
// Carried invariants (all verified by passing rounds):
//   - 5 cross taps always pass (max d2=2.5 < 9/pi=2.865) -> unconditional
//   - 12 ring taps: load only when d2 < KW2 (w>0 inside => window+max(0,.)
//     reproduced exactly); (+-2,+-2) corners statically pruned (min d2=4.5)
//   - prep kernel folds per-LOR setup into fx(kz)=Ax+Bx*kz, fy(kz)=Ay+By*kz
//   - g_imgT selected DEVICE-side (TPOSE bool) for stride-1 walks everywhere
// ---------------------------------------------------------------------------

#define G 128
#define GSQ (G * G)
#define MAX_LORS (1 << 20)
#define WARPS_PER_BLOCK 8

__device__ float  g_imgT[G * G * G];          // transposed image for px frame
__device__ float4 g_prm[3][MAX_LORS];         // Ax, Bx, Ay, By
__device__ float  g_stp[3][MAX_LORS];         // step

// g_imgT[a][c][b] = in[a][b][c]
__global__ void transpose_bc_kernel(const float* __restrict__ in) {
    __shared__ float tile[32][33];
    const int a  = blockIdx.z;
    const int b0 = blockIdx.y * 32;
    const int c0 = blockIdx.x * 32;
    const float* src = in     + (size_t)a * GSQ;
    float*       dst = g_imgT + (size_t)a * GSQ;
#pragma unroll
    for (int i = threadIdx.y; i < 32; i += 8)
        tile[i][threadIdx.x] = src[(b0 + i) * G + c0 + threadIdx.x];
    __syncthreads();
#pragma unroll
    for (int i = threadIdx.y; i < 32; i += 8)
        dst[(c0 + i) * G + b0 + threadIdx.x] = tile[threadIdx.x][i];
}

// One thread per LOR. P0/P1/P2 permute grid/center/size ONLY (lors are
// already frame-local — verified by passing rounds).
template <int P0, int P1, int P2>
__global__ void prep_kernel(const int*   __restrict__ grid,
                            const float* __restrict__ center,
                            const float* __restrict__ size,
                            const float* __restrict__ lors,
                            int n, int set)
{
    int i = blockIdx.x * blockDim.x + threadIdx.x;
    if (i >= n) return;
    const float sz0 = size[P0], sz1 = size[P1], sz2 = size[P2];
    const int   n0 = grid[P0], n1 = grid[P1], n2 = grid[P2];
    const float vs0 = sz0 / (float)n0;
    const float vs1 = sz1 / (float)n1;
    const float vs2 = sz2 / (float)n2;
    const float lo0 = center[P0] - 0.5f * sz0;
    const float lo1 = center[P1] - 0.5f * sz1;
    const float lo2 = center[P2] - 0.5f * sz2;

    const float* L = lors + (size_t)i * 6;
    const float p10 = L[0], p11 = L[1], p12 = L[2];
    const float d0  = L[3] - p10;
    const float d1  = L[4] - p11;
    const float d2c = L[5] - p12;
    const float len = sqrtf(d0 * d0 + d1 * d1 + d2c * d2c);
    const float inv_dz = 1.0f / d2c;
    const float t0 = (lo2 + 0.5f * vs2 - p12) * inv_dz;   // t(kz)=t0+kz*dt
    const float dt = vs2 * inv_dz;
    const float Ax = (p10 + t0 * d0 - lo0) / vs0 - 0.5f;
    const float Bx = dt * d0 / vs0;
    const float Ay = (p11 + t0 * d1 - lo1) / vs1 - 0.5f;
    const float By = dt * d1 / vs1;
    g_prm[set][i] = make_float4(Ax, Bx, Ay, By);
    g_stp[set][i] = vs2 * len / fabsf(d2c);
}

// sqrt(d2) via one MUFU.RSQ + FMUL (rel err ~2^-22; exact 0 at d2=0).
__device__ __forceinline__ float fast_sqrt(float d2) {
    return d2 * rsqrtf(fmaxf(d2, 1e-30f));
}

// Hot kernel: one WARP per LOR; lane handles kz = lane + 32j, j=0..3.
template <int S0, int S1, bool TPOSE>
__global__ __launch_bounds__(32 * WARPS_PER_BLOCK)
void tor_fast_kernel(const float* __restrict__ img_in, int set,
                     float* __restrict__ out, int n_lors)
{
    const float* img = TPOSE ? (const float*)g_imgT : img_in;

    const int warp = threadIdx.x >> 5;
    const int lane = threadIdx.x & 31;
    const int lor  = blockIdx.x * WARPS_PER_BLOCK + warp;
    if (lor >= n_lors) return;

    const float4 P = __ldg(&g_prm[set][lor]);

    const float KW2    = 2.8647889756541160f;   // 9/pi
    const float INV_KW = 0.59081795026046127f;  // 1/sqrt(9/pi)

    float acc = 0.0f;

#pragma unroll
    for (int j = 0; j < 4; ++j) {
        const int   kz  = lane + 32 * j;
        const float kzf = (float)kz;
        const float fx = fmaf(kzf, P.y, P.x);
        const float fy = fmaf(kzf, P.w, P.z);
        const int ix = __float2int_rn(fx);   // half-to-even == jnp.round
        const int iy = __float2int_rn(fy);

        const float ux = (float)ix - fx;     // in [-0.5, 0.5]
        const float uy = (float)iy - fy;
        float xs[5], ys[5];
#pragma unroll
        for (int o = 0; o < 5; ++o) {
            const float a = ux + (float)(o - 2);
            const float b = uy + (float)(o - 2);
            xs[o] = a * a;
            ys[o] = b * b;
        }

        if ((unsigned)(ix - 2) <= (unsigned)(G - 5) &&
            (unsigned)(iy - 2) <= (unsigned)(G - 5)) {
            const float* p = img + ix * S0 + iy * S1 + kz;
#pragma unroll
            for (int o0 = -2; o0 <= 2; ++o0) {
#pragma unroll
                for (int o1 = -2; o1 <= 2; ++o1) {
                    const int r2 = o0 * o0 + o1 * o1;
                    if (r2 == 8) continue;               // corners: never pass
                    const float d2 = xs[o0 + 2] + ys[o1 + 2];
                    if (r2 <= 1) {
                        // cross taps: always pass, w>0 guaranteed
                        const float w = fmaf(-fast_sqrt(d2), INV_KW, 1.0f);
                        acc = fmaf(w, __ldg(p + (o0 * S0 + o1 * S1)), acc);
                    } else if (d2 < KW2) {
                        // ring taps: load only when weight positive
                        const float w = fmaf(-fast_sqrt(d2), INV_KW, 1.0f);
                        acc = fmaf(w, __ldg(p + (o0 * S0 + o1 * S1)), acc);
                    }
                }
            }
        } else {
            // edge fallback (not hit for this dataset): per-tap bounds
#pragma unroll
            for (int o0 = -2; o0 <= 2; ++o0) {
#pragma unroll
                for (int o1 = -2; o1 <= 2; ++o1) {
                    if (o0 * o0 + o1 * o1 == 8) continue;
                    const int jx = ix + o0;
                    const int jy = iy + o1;
                    const float d2 = xs[o0 + 2] + ys[o1 + 2];
                    if (d2 < KW2 && (unsigned)jx < (unsigned)G && (unsigned)jy < (unsigned)G) {
                        const float w = fmaf(-fast_sqrt(d2), INV_KW, 1.0f);
                        acc = fmaf(w, __ldg(img + jx * S0 + jy * S1 + kz), acc);
                    }
                }
            }
        }
    }

    // warp reduction
#pragma unroll
    for (int sft = 16; sft > 0; sft >>= 1)
        acc += __shfl_down_sync(0xFFFFFFFFu, acc, sft);
    if (lane == 0)
        out[lor] = acc * __ldg(&g_stp[set][lor]);
}

// ------------------------ generic fallback -----------------------------------
template <int P0, int P1, int P2>
__global__ __launch_bounds__(128)
void tor_generic_kernel(const float* __restrict__ img_in,
                        const int*   __restrict__ grid,
                        const float* __restrict__ center,
                        const float* __restrict__ size,
                        const float* __restrict__ lors,
                        float*       __restrict__ out,
                        int n_lors)
{
    const int lor = blockIdx.x;
    if (lor >= n_lors) return;
    const int g0 = grid[0], g1 = grid[1], g2 = grid[2];
    const int gs[3]   = { g0, g1, g2 };
    const int istr[3] = { g1 * g2, g2, 1 };
    const int n0 = gs[P0], n1 = gs[P1], n2 = gs[P2];
    const int s0 = istr[P0], s1 = istr[P1], s2 = istr[P2];
    const float* img = img_in;

    const float sz0 = size[P0], sz1 = size[P1], sz2 = size[P2];
    const float vs0 = sz0 / (float)n0, vs1 = sz1 / (float)n1, vs2 = sz2 / (float)n2;
    const float lo0 = center[P0] - sz0 * 0.5f;
    const float lo1 = center[P1] - sz1 * 0.5f;
    const float lo2 = center[P2] - sz2 * 0.5f;

    const float* L = lors + (size_t)lor * 6;
    const float p1x = __ldg(L + 0), p1y = __ldg(L + 1), p1z = __ldg(L + 2);
    const float dx = __ldg(L + 3) - p1x, dy = __ldg(L + 4) - p1y, dz = __ldg(L + 5) - p1z;
    const float len = sqrtf(dx * dx + dy * dy + dz * dz);
    const float step = vs2 * len / fabsf(dz);
    const float inv_dz = 1.0f / dz, inv_vs0 = 1.0f / vs0, inv_vs1 = 1.0f / vs1;
    const float KW2 = 2.8647889756541160f, INV_KW = 0.59081795026046127f;

    float acc = 0.0f;
    for (int kz = threadIdx.x; kz < n2; kz += blockDim.x) {
        const float zc = lo2 + ((float)kz + 0.5f) * vs2;
        const float t  = (zc - p1z) * inv_dz;
        const float fx = (fmaf(t, dx, p1x) - lo0) * inv_vs0 - 0.5f;
        const float fy = (fmaf(t, dy, p1y) - lo1) * inv_vs1 - 0.5f;
        const int ix = __float2int_rn(fx);
        const int iy = __float2int_rn(fy);
#pragma unroll
        for (int o0 = -2; o0 <= 2; ++o0) {
#pragma unroll
            for (int o1 = -2; o1 <= 2; ++o1) {
                if (o0 * o0 + o1 * o1 == 8) continue;
                const int jx = ix + o0, jy = iy + o1;
                const float ddx = (float)jx - fx, ddy = (float)jy - fy;
                const float d2 = ddx * ddx + ddy * ddy;
                if (d2 < KW2 && (unsigned)jx < (unsigned)n0 && (unsigned)jy < (unsigned)n1) {
                    const float s = d2 * rsqrtf(fmaxf(d2, 1e-30f));
                    const float w = fmaf(-s, INV_KW, 1.0f);
                    acc = fmaf(w, __ldg(&img[jx * s0 + jy * s1 + kz * s2]), acc);
                }
            }
        }
    }
#pragma unroll
    for (int sft = 16; sft > 0; sft >>= 1)
        acc += __shfl_down_sync(0xFFFFFFFFu, acc, sft);
    __shared__ float wsum[4];
    if ((threadIdx.x & 31) == 0) wsum[threadIdx.x >> 5] = acc;
    __syncthreads();
    if (threadIdx.x == 0)
        out[lor] = (wsum[0] + wsum[1] + wsum[2] + wsum[3]) * step;
}

extern "C" void kernel_launch(void* const* d_in, const int* in_sizes, int n_in,
                              void* d_out, int out_size)
{
    const float* image  = (const float*)d_in[0];
    const int*   grid   = (const int*)  d_in[1];
    const float* center = (const float*)d_in[2];
    const float* size   = (const float*)d_in[3];
    const float* xlors  = (const float*)d_in[4];
    const float* ylors  = (const float*)d_in[5];
    const float* zlors  = (const float*)d_in[6];
    float* out = (float*)d_out;

    const int nx = in_sizes[4] / 6;
    const int ny = in_sizes[5] / 6;
    const int nz = in_sizes[6] / 6;

    const long long nimg = in_sizes[0];
    const bool fast = (nimg == (long long)G * G * G) &&
                      nx <= MAX_LORS && ny <= MAX_LORS && nz <= MAX_LORS;

    if (fast) {
        {   // transpose for px frame (walked image axis must be stride-1)
            dim3 tb(32, 8), tg(G / 32, G / 32, G);
            transpose_bc_kernel<<<tg, tb>>>(image);
        }
        const int PT = 256;
        if (nx > 0) prep_kernel<2, 0, 1><<<(nx + PT - 1) / PT, PT>>>(grid, center, size, xlors, nx, 0);
        if (ny > 0) prep_kernel<1, 0, 2><<<(ny + PT - 1) / PT, PT>>>(grid, center, size, ylors, ny, 1);
        if (nz > 0) prep_kernel<0, 1, 2><<<(nz + PT - 1) / PT, PT>>>(grid, center, size, zlors, nz, 2);

        const int W = WARPS_PER_BLOCK;
        // px: image[jy][kz][jx] = g_imgT[jy][jx][kz] -> S0=G, S1=GSQ (TPOSE)
        if (nx > 0) tor_fast_kernel<G,   GSQ, true ><<<(nx + W - 1) / W, 32 * W>>>(image, 0, out, nx);
        // py: image[jy][jx][kz] -> S0=G, S1=GSQ
        if (ny > 0) tor_fast_kernel<G,   GSQ, false><<<(ny + W - 1) / W, 32 * W>>>(image, 1, out + nx, ny);
        // pz: image[jx][jy][kz] -> S0=GSQ, S1=G
        if (nz > 0) tor_fast_kernel<GSQ, G,   false><<<(nz + W - 1) / W, 32 * W>>>(image, 2, out + nx + ny, nz);
    } else {
        if (nx > 0) tor_generic_kernel<2, 0, 1><<<nx, 128>>>(image, grid, center, size, xlors, out, nx);
        if (ny > 0) tor_generic_kernel<1, 0, 2><<<ny, 128>>>(image, grid, center, size, ylors, out + nx, ny);
        if (nz > 0) tor_generic_kernel<0, 1, 2><<<nz, 128>>>(image, grid, center, size, zlors, out + nx + ny, nz);
    }
}

// round 10
// speedup vs baseline: 2.4845x; 1.0184x over previous
#include <cuda_runtime.h>
#include <math.h>

// ---------------------------------------------------------------------------
// Projection_12438225290005: tube-of-response projection, 3 axis frames.
//
// R9 = R8 + accumulation-chain fix. R8 timed 1190 SMSP-cyc/warp-LOR against
// ~670 issued warp-inst: the single `acc` register chained all 68 taps
// (68 x FFMA lat 4 = 272 cyc dependent chain, fed by MUFU lat 16). Split into
// two parity accumulators with per-group temporaries -> chain ~36 cyc,
// 4 j-groups independent. Also drop the fmax guard in fast_sqrt for every
// tap except (0,0) (all others have d2 >= 0.25 by construction).
//
// Carried invariants (verified by passing rounds):
//   - 5 cross taps always pass (max d2=2.5 < 9/pi=2.865) -> unconditional
//   - 12 ring taps: load only when d2 < KW2 (w>0 inside => window+max(0,.)
//     reproduced exactly); (+-2,+-2) corners statically pruned (min d2=4.5)
//   - sqrt(d2) = d2 * rsqrt(d2): one MUFU.RSQ+FMUL, rel err ~2^-22
//   - prep kernel folds per-LOR setup into fx(kz)=Ax+Bx*kz, fy(kz)=Ay+By*kz
//   - g_imgT selected DEVICE-side (TPOSE bool) for stride-1 walks everywhere
// ---------------------------------------------------------------------------

#define G 128
#define GSQ (G * G)
#define MAX_LORS (1 << 20)
#define WARPS_PER_BLOCK 8

__device__ float  g_imgT[G * G * G];          // transposed image for px frame
__device__ float4 g_prm[3][MAX_LORS];         // Ax, Bx, Ay, By
__device__ float  g_stp[3][MAX_LORS];         // step

// g_imgT[a][c][b] = in[a][b][c]
__global__ void transpose_bc_kernel(const float* __restrict__ in) {
    __shared__ float tile[32][33];
    const int a  = blockIdx.z;
    const int b0 = blockIdx.y * 32;
    const int c0 = blockIdx.x * 32;
    const float* src = in     + (size_t)a * GSQ;
    float*       dst = g_imgT + (size_t)a * GSQ;
#pragma unroll
    for (int i = threadIdx.y; i < 32; i += 8)
        tile[i][threadIdx.x] = src[(b0 + i) * G + c0 + threadIdx.x];
    __syncthreads();
#pragma unroll
    for (int i = threadIdx.y; i < 32; i += 8)
        dst[(c0 + i) * G + b0 + threadIdx.x] = tile[threadIdx.x][i];
}

// One thread per LOR. P0/P1/P2 permute grid/center/size ONLY (lors are
// already frame-local — verified by passing rounds).
template <int P0, int P1, int P2>
__global__ void prep_kernel(const int*   __restrict__ grid,
                            const float* __restrict__ center,
                            const float* __restrict__ size,
                            const float* __restrict__ lors,
                            int n, int set)
{
    int i = blockIdx.x * blockDim.x + threadIdx.x;
    if (i >= n) return;
    const float sz0 = size[P0], sz1 = size[P1], sz2 = size[P2];
    const int   n0 = grid[P0], n1 = grid[P1], n2 = grid[P2];
    const float vs0 = sz0 / (float)n0;
    const float vs1 = sz1 / (float)n1;
    const float vs2 = sz2 / (float)n2;
    const float lo0 = center[P0] - 0.5f * sz0;
    const float lo1 = center[P1] - 0.5f * sz1;
    const float lo2 = center[P2] - 0.5f * sz2;

    const float* L = lors + (size_t)i * 6;
    const float p10 = L[0], p11 = L[1], p12 = L[2];
    const float d0  = L[3] - p10;
    const float d1  = L[4] - p11;
    const float d2c = L[5] - p12;
    const float len = sqrtf(d0 * d0 + d1 * d1 + d2c * d2c);
    const float inv_dz = 1.0f / d2c;
    const float t0 = (lo2 + 0.5f * vs2 - p12) * inv_dz;   // t(kz)=t0+kz*dt
    const float dt = vs2 * inv_dz;
    const float Ax = (p10 + t0 * d0 - lo0) / vs0 - 0.5f;
    const float Bx = dt * d0 / vs0;
    const float Ay = (p11 + t0 * d1 - lo1) / vs1 - 0.5f;
    const float By = dt * d1 / vs1;
    g_prm[set][i] = make_float4(Ax, Bx, Ay, By);
    g_stp[set][i] = vs2 * len / fabsf(d2c);
}

// sqrt(d2) via one MUFU.RSQ + FMUL. Guarded variant only for d2 that can be 0.
__device__ __forceinline__ float fast_sqrt_guard(float d2) {
    return d2 * rsqrtf(fmaxf(d2, 1e-30f));
}
__device__ __forceinline__ float fast_sqrt_nz(float d2) {   // d2 >= 0.25
    return d2 * rsqrtf(d2);
}

// Hot kernel: one WARP per LOR; lane handles kz = lane + 32j, j=0..3.
template <int S0, int S1, bool TPOSE>
__global__ __launch_bounds__(32 * WARPS_PER_BLOCK)
void tor_fast_kernel(const float* __restrict__ img_in, int set,
                     float* __restrict__ out, int n_lors)
{
    const float* img = TPOSE ? (const float*)g_imgT : img_in;

    const int warp = threadIdx.x >> 5;
    const int lane = threadIdx.x & 31;
    const int lor  = blockIdx.x * WARPS_PER_BLOCK + warp;
    if (lor >= n_lors) return;

    const float4 P = __ldg(&g_prm[set][lor]);

    const float KW2    = 2.8647889756541160f;   // 9/pi
    const float INV_KW = 0.59081795026046127f;  // 1/sqrt(9/pi)

    float accE = 0.0f, accO = 0.0f;   // parity-split accumulators

#pragma unroll
    for (int j = 0; j < 4; ++j) {
        const int   kz  = lane + 32 * j;
        const float kzf = (float)kz;
        const float fx = fmaf(kzf, P.y, P.x);
        const float fy = fmaf(kzf, P.w, P.z);
        const int ix = __float2int_rn(fx);   // half-to-even == jnp.round
        const int iy = __float2int_rn(fy);

        const float ux = (float)ix - fx;     // in [-0.5, 0.5]
        const float uy = (float)iy - fy;
        float xs[5], ys[5];
#pragma unroll
        for (int o = 0; o < 5; ++o) {
            const float a = ux + (float)(o - 2);
            const float b = uy + (float)(o - 2);
            xs[o] = a * a;
            ys[o] = b * b;
        }

        float t0 = 0.0f, t1 = 0.0f;        // per-group temporaries (2 chains)

        if ((unsigned)(ix - 2) <= (unsigned)(G - 5) &&
            (unsigned)(iy - 2) <= (unsigned)(G - 5)) {
            const float* p = img + ix * S0 + iy * S1 + kz;
#pragma unroll
            for (int o0 = -2; o0 <= 2; ++o0) {
#pragma unroll
                for (int o1 = -2; o1 <= 2; ++o1) {
                    const int r2 = o0 * o0 + o1 * o1;
                    if (r2 == 8) continue;               // corners: never pass
                    const float d2 = xs[o0 + 2] + ys[o1 + 2];
                    const bool even = (((o0 + o1) & 1) == 0);
                    if (r2 == 0) {
                        // center tap: always pass, d2 may be 0 -> guarded sqrt
                        const float w = fmaf(-fast_sqrt_guard(d2), INV_KW, 1.0f);
                        t0 = fmaf(w, __ldg(p), t0);
                    } else if (r2 <= 1) {
                        // other cross taps: always pass, d2 >= 0.25
                        const float w = fmaf(-fast_sqrt_nz(d2), INV_KW, 1.0f);
                        const float v = __ldg(p + (o0 * S0 + o1 * S1));
                        if (even) t0 = fmaf(w, v, t0); else t1 = fmaf(w, v, t1);
                    } else if (d2 < KW2) {
                        // ring taps: load only when weight positive (d2 >= 0.5)
                        const float w = fmaf(-fast_sqrt_nz(d2), INV_KW, 1.0f);
                        const float v = __ldg(p + (o0 * S0 + o1 * S1));
                        if (even) t0 = fmaf(w, v, t0); else t1 = fmaf(w, v, t1);
                    }
                }
            }
        } else {
            // edge fallback (not hit for this dataset): per-tap bounds
#pragma unroll
            for (int o0 = -2; o0 <= 2; ++o0) {
#pragma unroll
                for (int o1 = -2; o1 <= 2; ++o1) {
                    if (o0 * o0 + o1 * o1 == 8) continue;
                    const int jx = ix + o0;
                    const int jy = iy + o1;
                    const float d2 = xs[o0 + 2] + ys[o1 + 2];
                    if (d2 < KW2 && (unsigned)jx < (unsigned)G && (unsigned)jy < (unsigned)G) {
                        const float w = fmaf(-fast_sqrt_guard(d2), INV_KW, 1.0f);
                        t0 = fmaf(w, __ldg(img + jx * S0 + jy * S1 + kz), t0);
                    }
                }
            }
        }

        accE += t0;
        accO += t1;
    }

    float acc = accE + accO;

    // warp reduction
#pragma unroll
    for (int sft = 16; sft > 0; sft >>= 1)
        acc += __shfl_down_sync(0xFFFFFFFFu, acc, sft);
    if (lane == 0)
        out[lor] = acc * __ldg(&g_stp[set][lor]);
}

// ------------------------ generic fallback -----------------------------------
template <int P0, int P1, int P2>
__global__ __launch_bounds__(128)
void tor_generic_kernel(const float* __restrict__ img_in,
                        const int*   __restrict__ grid,
                        const float* __restrict__ center,
                        const float* __restrict__ size,
                        const float* __restrict__ lors,
                        float*       __restrict__ out,
                        int n_lors)
{
    const int lor = blockIdx.x;
    if (lor >= n_lors) return;
    const int g0 = grid[0], g1 = grid[1], g2 = grid[2];
    const int gs[3]   = { g0, g1, g2 };
    const int istr[3] = { g1 * g2, g2, 1 };
    const int n0 = gs[P0], n1 = gs[P1], n2 = gs[P2];
    const int s0 = istr[P0], s1 = istr[P1], s2 = istr[P2];
    const float* img = img_in;

    const float sz0 = size[P0], sz1 = size[P1], sz2 = size[P2];
    const float vs0 = sz0 / (float)n0, vs1 = sz1 / (float)n1, vs2 = sz2 / (float)n2;
    const float lo0 = center[P0] - sz0 * 0.5f;
    const float lo1 = center[P1] - sz1 * 0.5f;
    const float lo2 = center[P2] - sz2 * 0.5f;

    const float* L = lors + (size_t)lor * 6;
    const float p1x = __ldg(L + 0), p1y = __ldg(L + 1), p1z = __ldg(L + 2);
    const float dx = __ldg(L + 3) - p1x, dy = __ldg(L + 4) - p1y, dz = __ldg(L + 5) - p1z;
    const float len = sqrtf(dx * dx + dy * dy + dz * dz);
    const float step = vs2 * len / fabsf(dz);
    const float inv_dz = 1.0f / dz, inv_vs0 = 1.0f / vs0, inv_vs1 = 1.0f / vs1;
    const float KW2 = 2.8647889756541160f, INV_KW = 0.59081795026046127f;

    float acc = 0.0f;
    for (int kz = threadIdx.x; kz < n2; kz += blockDim.x) {
        const float zc = lo2 + ((float)kz + 0.5f) * vs2;
        const float t  = (zc - p1z) * inv_dz;
        const float fx = (fmaf(t, dx, p1x) - lo0) * inv_vs0 - 0.5f;
        const float fy = (fmaf(t, dy, p1y) - lo1) * inv_vs1 - 0.5f;
        const int ix = __float2int_rn(fx);
        const int iy = __float2int_rn(fy);
#pragma unroll
        for (int o0 = -2; o0 <= 2; ++o0) {
#pragma unroll
            for (int o1 = -2; o1 <= 2; ++o1) {
                if (o0 * o0 + o1 * o1 == 8) continue;
                const int jx = ix + o0, jy = iy + o1;
                const float ddx = (float)jx - fx, ddy = (float)jy - fy;
                const float d2 = ddx * ddx + ddy * ddy;
                if (d2 < KW2 && (unsigned)jx < (unsigned)n0 && (unsigned)jy < (unsigned)n1) {
                    const float s = d2 * rsqrtf(fmaxf(d2, 1e-30f));
                    const float w = fmaf(-s, INV_KW, 1.0f);
                    acc = fmaf(w, __ldg(&img[jx * s0 + jy * s1 + kz * s2]), acc);
                }
            }
        }
    }
#pragma unroll
    for (int sft = 16; sft > 0; sft >>= 1)
        acc += __shfl_down_sync(0xFFFFFFFFu, acc, sft);
    __shared__ float wsum[4];
    if ((threadIdx.x & 31) == 0) wsum[threadIdx.x >> 5] = acc;
    __syncthreads();
    if (threadIdx.x == 0)
        out[lor] = (wsum[0] + wsum[1] + wsum[2] + wsum[3]) * step;
}

extern "C" void kernel_launch(void* const* d_in, const int* in_sizes, int n_in,
                              void* d_out, int out_size)
{
    const float* image  = (const float*)d_in[0];
    const int*   grid   = (const int*)  d_in[1];
    const float* center = (const float*)d_in[2];
    const float* size   = (const float*)d_in[3];
    const float* xlors  = (const float*)d_in[4];
    const float* ylors  = (const float*)d_in[5];
    const float* zlors  = (const float*)d_in[6];
    float* out = (float*)d_out;

    const int nx = in_sizes[4] / 6;
    const int ny = in_sizes[5] / 6;
    const int nz = in_sizes[6] / 6;

    const long long nimg = in_sizes[0];
    const bool fast = (nimg == (long long)G * G * G) &&
                      nx <= MAX_LORS && ny <= MAX_LORS && nz <= MAX_LORS;

    if (fast) {
        {   // transpose for px frame (walked image axis must be stride-1)
            dim3 tb(32, 8), tg(G / 32, G / 32, G);
            transpose_bc_kernel<<<tg, tb>>>(image);
        }
        const int PT = 256;
        if (nx > 0) prep_kernel<2, 0, 1><<<(nx + PT - 1) / PT, PT>>>(grid, center, size, xlors, nx, 0);
        if (ny > 0) prep_kernel<1, 0, 2><<<(ny + PT - 1) / PT, PT>>>(grid, center, size, ylors, ny, 1);
        if (nz > 0) prep_kernel<0, 1, 2><<<(nz + PT - 1) / PT, PT>>>(grid, center, size, zlors, nz, 2);

        const int W = WARPS_PER_BLOCK;
        // px: image[jy][kz][jx] = g_imgT[jy][jx][kz] -> S0=G, S1=GSQ (TPOSE)
        if (nx > 0) tor_fast_kernel<G,   GSQ, true ><<<(nx + W - 1) / W, 32 * W>>>(image, 0, out, nx);
        // py: image[jy][jx][kz] -> S0=G, S1=GSQ
        if (ny > 0) tor_fast_kernel<G,   GSQ, false><<<(ny + W - 1) / W, 32 * W>>>(image, 1, out + nx, ny);
        // pz: image[jx][jy][kz] -> S0=GSQ, S1=G
        if (nz > 0) tor_fast_kernel<GSQ, G,   false><<<(nz + W - 1) / W, 32 * W>>>(image, 2, out + nx + ny, nz);
    } else {
        if (nx > 0) tor_generic_kernel<2, 0, 1><<<nx, 128>>>(image, grid, center, size, xlors, out, nx);
        if (ny > 0) tor_generic_kernel<1, 0, 2><<<ny, 128>>>(image, grid, center, size, ylors, out + nx, ny);
        if (nz > 0) tor_generic_kernel<0, 1, 2><<<nz, 128>>>(image, grid, center, size, zlors, out + nx + ny, nz);
    }
}

// round 11
// speedup vs baseline: 2.5694x; 1.0342x over previous
#include <cuda_runtime.h>
#include <math.h>

// ---------------------------------------------------------------------------
// Projection_12438225290005: tube-of-response projection, 3 axis frames.
//
// R10 = R9 (best passing, 678us) + occupancy push + launch reorder.
//   - __launch_bounds__(256, 6): cap regs ~42 -> 48 warps/SM (12/SMSP, was ~8)
//     to cover L2-hit latency (~250cyc; image 8MB >> L1, every tap ~L2 hit).
//   - launch order prep x3 -> transpose -> fast x3 so ncu -s 5 captures a HOT
//     kernel instead of prep (instrumentation for the next round).
// Tap math unchanged from R9 (verified: rel_err 1.4e-7):
//   - 5 cross taps always pass (max d2=2.5 < 9/pi) -> unconditional load
//   - 12 ring taps: load only when d2 < KW2; corners statically pruned
//   - sqrt(d2) = d2*rsqrt(d2) (1 MUFU.RSQ+FMUL); guard only at center tap
//   - parity-split accumulators, per-group temporaries
//   - prep folds per-LOR setup into fx(kz)=Ax+Bx*kz, fy(kz)=Ay+By*kz
//   - g_imgT selected DEVICE-side (TPOSE bool) for stride-1 walks everywhere
// ---------------------------------------------------------------------------

#define G 128
#define GSQ (G * G)
#define MAX_LORS (1 << 20)
#define WARPS_PER_BLOCK 8

__device__ float  g_imgT[G * G * G];          // transposed image for px frame
__device__ float4 g_prm[3][MAX_LORS];         // Ax, Bx, Ay, By
__device__ float  g_stp[3][MAX_LORS];         // step

// g_imgT[a][c][b] = in[a][b][c]
__global__ void transpose_bc_kernel(const float* __restrict__ in) {
    __shared__ float tile[32][33];
    const int a  = blockIdx.z;
    const int b0 = blockIdx.y * 32;
    const int c0 = blockIdx.x * 32;
    const float* src = in     + (size_t)a * GSQ;
    float*       dst = g_imgT + (size_t)a * GSQ;
#pragma unroll
    for (int i = threadIdx.y; i < 32; i += 8)
        tile[i][threadIdx.x] = src[(b0 + i) * G + c0 + threadIdx.x];
    __syncthreads();
#pragma unroll
    for (int i = threadIdx.y; i < 32; i += 8)
        dst[(c0 + i) * G + b0 + threadIdx.x] = tile[threadIdx.x][i];
}

// One thread per LOR. P0/P1/P2 permute grid/center/size ONLY (lors are
// already frame-local — verified by passing rounds).
template <int P0, int P1, int P2>
__global__ void prep_kernel(const int*   __restrict__ grid,
                            const float* __restrict__ center,
                            const float* __restrict__ size,
                            const float* __restrict__ lors,
                            int n, int set)
{
    int i = blockIdx.x * blockDim.x + threadIdx.x;
    if (i >= n) return;
    const float sz0 = size[P0], sz1 = size[P1], sz2 = size[P2];
    const int   n0 = grid[P0], n1 = grid[P1], n2 = grid[P2];
    const float vs0 = sz0 / (float)n0;
    const float vs1 = sz1 / (float)n1;
    const float vs2 = sz2 / (float)n2;
    const float lo0 = center[P0] - 0.5f * sz0;
    const float lo1 = center[P1] - 0.5f * sz1;
    const float lo2 = center[P2] - 0.5f * sz2;

    const float* L = lors + (size_t)i * 6;
    const float p10 = L[0], p11 = L[1], p12 = L[2];
    const float d0  = L[3] - p10;
    const float d1  = L[4] - p11;
    const float d2c = L[5] - p12;
    const float len = sqrtf(d0 * d0 + d1 * d1 + d2c * d2c);
    const float inv_dz = 1.0f / d2c;
    const float t0 = (lo2 + 0.5f * vs2 - p12) * inv_dz;   // t(kz)=t0+kz*dt
    const float dt = vs2 * inv_dz;
    const float Ax = (p10 + t0 * d0 - lo0) / vs0 - 0.5f;
    const float Bx = dt * d0 / vs0;
    const float Ay = (p11 + t0 * d1 - lo1) / vs1 - 0.5f;
    const float By = dt * d1 / vs1;
    g_prm[set][i] = make_float4(Ax, Bx, Ay, By);
    g_stp[set][i] = vs2 * len / fabsf(d2c);
}

// sqrt(d2) via one MUFU.RSQ + FMUL. Guarded variant only for d2 that can be 0.
__device__ __forceinline__ float fast_sqrt_guard(float d2) {
    return d2 * rsqrtf(fmaxf(d2, 1e-30f));
}
__device__ __forceinline__ float fast_sqrt_nz(float d2) {   // d2 >= 0.25
    return d2 * rsqrtf(d2);
}

// Hot kernel: one WARP per LOR; lane handles kz = lane + 32j, j=0..3.
template <int S0, int S1, bool TPOSE>
__global__ __launch_bounds__(32 * WARPS_PER_BLOCK, 6)
void tor_fast_kernel(const float* __restrict__ img_in, int set,
                     float* __restrict__ out, int n_lors)
{
    const float* img = TPOSE ? (const float*)g_imgT : img_in;

    const int warp = threadIdx.x >> 5;
    const int lane = threadIdx.x & 31;
    const int lor  = blockIdx.x * WARPS_PER_BLOCK + warp;
    if (lor >= n_lors) return;

    const float4 P = __ldg(&g_prm[set][lor]);

    const float KW2    = 2.8647889756541160f;   // 9/pi
    const float INV_KW = 0.59081795026046127f;  // 1/sqrt(9/pi)

    float accE = 0.0f, accO = 0.0f;   // parity-split accumulators

#pragma unroll
    for (int j = 0; j < 4; ++j) {
        const int   kz  = lane + 32 * j;
        const float kzf = (float)kz;
        const float fx = fmaf(kzf, P.y, P.x);
        const float fy = fmaf(kzf, P.w, P.z);
        const int ix = __float2int_rn(fx);   // half-to-even == jnp.round
        const int iy = __float2int_rn(fy);

        const float ux = (float)ix - fx;     // in [-0.5, 0.5]
        const float uy = (float)iy - fy;
        float xs[5], ys[5];
#pragma unroll
        for (int o = 0; o < 5; ++o) {
            const float a = ux + (float)(o - 2);
            const float b = uy + (float)(o - 2);
            xs[o] = a * a;
            ys[o] = b * b;
        }

        float t0 = 0.0f, t1 = 0.0f;        // per-group temporaries (2 chains)

        if ((unsigned)(ix - 2) <= (unsigned)(G - 5) &&
            (unsigned)(iy - 2) <= (unsigned)(G - 5)) {
            const float* p = img + ix * S0 + iy * S1 + kz;
#pragma unroll
            for (int o0 = -2; o0 <= 2; ++o0) {
#pragma unroll
                for (int o1 = -2; o1 <= 2; ++o1) {
                    const int r2 = o0 * o0 + o1 * o1;
                    if (r2 == 8) continue;               // corners: never pass
                    const float d2 = xs[o0 + 2] + ys[o1 + 2];
                    const bool even = (((o0 + o1) & 1) == 0);
                    if (r2 == 0) {
                        // center tap: always pass, d2 may be 0 -> guarded sqrt
                        const float w = fmaf(-fast_sqrt_guard(d2), INV_KW, 1.0f);
                        t0 = fmaf(w, __ldg(p), t0);
                    } else if (r2 <= 1) {
                        // other cross taps: always pass, d2 >= 0.25
                        const float w = fmaf(-fast_sqrt_nz(d2), INV_KW, 1.0f);
                        const float v = __ldg(p + (o0 * S0 + o1 * S1));
                        if (even) t0 = fmaf(w, v, t0); else t1 = fmaf(w, v, t1);
                    } else if (d2 < KW2) {
                        // ring taps: load only when weight positive (d2 >= 0.5)
                        const float w = fmaf(-fast_sqrt_nz(d2), INV_KW, 1.0f);
                        const float v = __ldg(p + (o0 * S0 + o1 * S1));
                        if (even) t0 = fmaf(w, v, t0); else t1 = fmaf(w, v, t1);
                    }
                }
            }
        } else {
            // edge fallback (not hit for this dataset): per-tap bounds
#pragma unroll
            for (int o0 = -2; o0 <= 2; ++o0) {
#pragma unroll
                for (int o1 = -2; o1 <= 2; ++o1) {
                    if (o0 * o0 + o1 * o1 == 8) continue;
                    const int jx = ix + o0;
                    const int jy = iy + o1;
                    const float d2 = xs[o0 + 2] + ys[o1 + 2];
                    if (d2 < KW2 && (unsigned)jx < (unsigned)G && (unsigned)jy < (unsigned)G) {
                        const float w = fmaf(-fast_sqrt_guard(d2), INV_KW, 1.0f);
                        t0 = fmaf(w, __ldg(img + jx * S0 + jy * S1 + kz), t0);
                    }
                }
            }
        }

        accE += t0;
        accO += t1;
    }

    float acc = accE + accO;

    // warp reduction
#pragma unroll
    for (int sft = 16; sft > 0; sft >>= 1)
        acc += __shfl_down_sync(0xFFFFFFFFu, acc, sft);
    if (lane == 0)
        out[lor] = acc * __ldg(&g_stp[set][lor]);
}

// ------------------------ generic fallback -----------------------------------
template <int P0, int P1, int P2>
__global__ __launch_bounds__(128)
void tor_generic_kernel(const float* __restrict__ img_in,
                        const int*   __restrict__ grid,
                        const float* __restrict__ center,
                        const float* __restrict__ size,
                        const float* __restrict__ lors,
                        float*       __restrict__ out,
                        int n_lors)
{
    const int lor = blockIdx.x;
    if (lor >= n_lors) return;
    const int g0 = grid[0], g1 = grid[1], g2 = grid[2];
    const int gs[3]   = { g0, g1, g2 };
    const int istr[3] = { g1 * g2, g2, 1 };
    const int n0 = gs[P0], n1 = gs[P1], n2 = gs[P2];
    const int s0 = istr[P0], s1 = istr[P1], s2 = istr[P2];
    const float* img = img_in;

    const float sz0 = size[P0], sz1 = size[P1], sz2 = size[P2];
    const float vs0 = sz0 / (float)n0, vs1 = sz1 / (float)n1, vs2 = sz2 / (float)n2;
    const float lo0 = center[P0] - sz0 * 0.5f;
    const float lo1 = center[P1] - sz1 * 0.5f;
    const float lo2 = center[P2] - sz2 * 0.5f;

    const float* L = lors + (size_t)lor * 6;
    const float p1x = __ldg(L + 0), p1y = __ldg(L + 1), p1z = __ldg(L + 2);
    const float dx = __ldg(L + 3) - p1x, dy = __ldg(L + 4) - p1y, dz = __ldg(L + 5) - p1z;
    const float len = sqrtf(dx * dx + dy * dy + dz * dz);
    const float step = vs2 * len / fabsf(dz);
    const float inv_dz = 1.0f / dz, inv_vs0 = 1.0f / vs0, inv_vs1 = 1.0f / vs1;
    const float KW2 = 2.8647889756541160f, INV_KW = 0.59081795026046127f;

    float acc = 0.0f;
    for (int kz = threadIdx.x; kz < n2; kz += blockDim.x) {
        const float zc = lo2 + ((float)kz + 0.5f) * vs2;
        const float t  = (zc - p1z) * inv_dz;
        const float fx = (fmaf(t, dx, p1x) - lo0) * inv_vs0 - 0.5f;
        const float fy = (fmaf(t, dy, p1y) - lo1) * inv_vs1 - 0.5f;
        const int ix = __float2int_rn(fx);
        const int iy = __float2int_rn(fy);
#pragma unroll
        for (int o0 = -2; o0 <= 2; ++o0) {
#pragma unroll
            for (int o1 = -2; o1 <= 2; ++o1) {
                if (o0 * o0 + o1 * o1 == 8) continue;
                const int jx = ix + o0, jy = iy + o1;
                const float ddx = (float)jx - fx, ddy = (float)jy - fy;
                const float d2 = ddx * ddx + ddy * ddy;
                if (d2 < KW2 && (unsigned)jx < (unsigned)n0 && (unsigned)jy < (unsigned)n1) {
                    const float s = d2 * rsqrtf(fmaxf(d2, 1e-30f));
                    const float w = fmaf(-s, INV_KW, 1.0f);
                    acc = fmaf(w, __ldg(&img[jx * s0 + jy * s1 + kz * s2]), acc);
                }
            }
        }
    }
#pragma unroll
    for (int sft = 16; sft > 0; sft >>= 1)
        acc += __shfl_down_sync(0xFFFFFFFFu, acc, sft);
    __shared__ float wsum[4];
    if ((threadIdx.x & 31) == 0) wsum[threadIdx.x >> 5] = acc;
    __syncthreads();
    if (threadIdx.x == 0)
        out[lor] = (wsum[0] + wsum[1] + wsum[2] + wsum[3]) * step;
}

extern "C" void kernel_launch(void* const* d_in, const int* in_sizes, int n_in,
                              void* d_out, int out_size)
{
    const float* image  = (const float*)d_in[0];
    const int*   grid   = (const int*)  d_in[1];
    const float* center = (const float*)d_in[2];
    const float* size   = (const float*)d_in[3];
    const float* xlors  = (const float*)d_in[4];
    const float* ylors  = (const float*)d_in[5];
    const float* zlors  = (const float*)d_in[6];
    float* out = (float*)d_out;

    const int nx = in_sizes[4] / 6;
    const int ny = in_sizes[5] / 6;
    const int nz = in_sizes[6] / 6;

    const long long nimg = in_sizes[0];
    const bool fast = (nimg == (long long)G * G * G) &&
                      nx <= MAX_LORS && ny <= MAX_LORS && nz <= MAX_LORS;

    if (fast) {
        // prep first, transpose after, so ncu -s 5 lands on a HOT kernel
        const int PT = 256;
        if (nx > 0) prep_kernel<2, 0, 1><<<(nx + PT - 1) / PT, PT>>>(grid, center, size, xlors, nx, 0);
        if (ny > 0) prep_kernel<1, 0, 2><<<(ny + PT - 1) / PT, PT>>>(grid, center, size, ylors, ny, 1);
        if (nz > 0) prep_kernel<0, 1, 2><<<(nz + PT - 1) / PT, PT>>>(grid, center, size, zlors, nz, 2);
        {   // transpose for px frame (walked image axis must be stride-1)
            dim3 tb(32, 8), tg(G / 32, G / 32, G);
            transpose_bc_kernel<<<tg, tb>>>(image);
        }

        const int W = WARPS_PER_BLOCK;
        // px: image[jy][kz][jx] = g_imgT[jy][jx][kz] -> S0=G, S1=GSQ (TPOSE)
        if (nx > 0) tor_fast_kernel<G,   GSQ, true ><<<(nx + W - 1) / W, 32 * W>>>(image, 0, out, nx);
        // py: image[jy][jx][kz] -> S0=G, S1=GSQ
        if (ny > 0) tor_fast_kernel<G,   GSQ, false><<<(ny + W - 1) / W, 32 * W>>>(image, 1, out + nx, ny);
        // pz: image[jx][jy][kz] -> S0=GSQ, S1=G
        if (nz > 0) tor_fast_kernel<GSQ, G,   false><<<(nz + W - 1) / W, 32 * W>>>(image, 2, out + nx + ny, nz);
    } else {
        if (nx > 0) tor_generic_kernel<2, 0, 1><<<nx, 128>>>(image, grid, center, size, xlors, out, nx);
        if (ny > 0) tor_generic_kernel<1, 0, 2><<<ny, 128>>>(image, grid, center, size, ylors, out + nx, ny);
        if (nz > 0) tor_generic_kernel<0, 1, 2><<<nz, 128>>>(image, grid, center, size, zlors, out + nx + ny, nz);
    }
}

// round 12
// speedup vs baseline: 2.5695x; 1.0000x over previous
#include <cuda_runtime.h>
#include <math.h>

// ---------------------------------------------------------------------------
// Projection_12438225290005: tube-of-response projection, 3 axis frames.
//
// R11 = R10 math (best passing, 655us) + launch reorder so the ncu capture
// (which empirically lands on the 4th kernel launch: R2 pz=#4, R9 prep=#4,
// R10 transpose=#4) finally profiles a HOT kernel (fast pz at slot #4).
// Hypothesis to verify next round: L1tex wavefront wall ~100% (row-drift
// breaks each warp tap-load into ~8-16 address runs), MUFU ~43%, issue ~40%.
//
// Carried invariants (verified by passing rounds):
//   - 5 cross taps always pass (max d2=2.5 < 9/pi=2.865) -> unconditional
//   - 12 ring taps: load only when d2 < KW2; corners statically pruned
//   - sqrt(d2) = d2*rsqrt(d2) (1 MUFU.RSQ+FMUL); guard only at center tap
//   - parity-split accumulators, per-group temporaries (ILP)
//   - prep folds per-LOR setup into fx(kz)=Ax+Bx*kz, fy(kz)=Ay+By*kz
//   - g_imgT selected DEVICE-side (TPOSE bool) for stride-1 walks everywhere
//   - __launch_bounds__(256, 6): 48 warps/SM
// ---------------------------------------------------------------------------

#define G 128
#define GSQ (G * G)
#define MAX_LORS (1 << 20)
#define WARPS_PER_BLOCK 8

__device__ float  g_imgT[G * G * G];          // transposed image for px frame
__device__ float4 g_prm[3][MAX_LORS];         // Ax, Bx, Ay, By
__device__ float  g_stp[3][MAX_LORS];         // step

// g_imgT[a][c][b] = in[a][b][c]
__global__ void transpose_bc_kernel(const float* __restrict__ in) {
    __shared__ float tile[32][33];
    const int a  = blockIdx.z;
    const int b0 = blockIdx.y * 32;
    const int c0 = blockIdx.x * 32;
    const float* src = in     + (size_t)a * GSQ;
    float*       dst = g_imgT + (size_t)a * GSQ;
#pragma unroll
    for (int i = threadIdx.y; i < 32; i += 8)
        tile[i][threadIdx.x] = src[(b0 + i) * G + c0 + threadIdx.x];
    __syncthreads();
#pragma unroll
    for (int i = threadIdx.y; i < 32; i += 8)
        dst[(c0 + i) * G + b0 + threadIdx.x] = tile[threadIdx.x][i];
}

// One thread per LOR. P0/P1/P2 permute grid/center/size ONLY (lors are
// already frame-local — verified by passing rounds).
template <int P0, int P1, int P2>
__global__ void prep_kernel(const int*   __restrict__ grid,
                            const float* __restrict__ center,
                            const float* __restrict__ size,
                            const float* __restrict__ lors,
                            int n, int set)
{
    int i = blockIdx.x * blockDim.x + threadIdx.x;
    if (i >= n) return;
    const float sz0 = size[P0], sz1 = size[P1], sz2 = size[P2];
    const int   n0 = grid[P0], n1 = grid[P1], n2 = grid[P2];
    const float vs0 = sz0 / (float)n0;
    const float vs1 = sz1 / (float)n1;
    const float vs2 = sz2 / (float)n2;
    const float lo0 = center[P0] - 0.5f * sz0;
    const float lo1 = center[P1] - 0.5f * sz1;
    const float lo2 = center[P2] - 0.5f * sz2;

    const float* L = lors + (size_t)i * 6;
    const float p10 = L[0], p11 = L[1], p12 = L[2];
    const float d0  = L[3] - p10;
    const float d1  = L[4] - p11;
    const float d2c = L[5] - p12;
    const float len = sqrtf(d0 * d0 + d1 * d1 + d2c * d2c);
    const float inv_dz = 1.0f / d2c;
    const float t0 = (lo2 + 0.5f * vs2 - p12) * inv_dz;   // t(kz)=t0+kz*dt
    const float dt = vs2 * inv_dz;
    const float Ax = (p10 + t0 * d0 - lo0) / vs0 - 0.5f;
    const float Bx = dt * d0 / vs0;
    const float Ay = (p11 + t0 * d1 - lo1) / vs1 - 0.5f;
    const float By = dt * d1 / vs1;
    g_prm[set][i] = make_float4(Ax, Bx, Ay, By);
    g_stp[set][i] = vs2 * len / fabsf(d2c);
}

// sqrt(d2) via one MUFU.RSQ + FMUL. Guarded variant only for d2 that can be 0.
__device__ __forceinline__ float fast_sqrt_guard(float d2) {
    return d2 * rsqrtf(fmaxf(d2, 1e-30f));
}
__device__ __forceinline__ float fast_sqrt_nz(float d2) {   // d2 >= 0.25
    return d2 * rsqrtf(d2);
}

// Hot kernel: one WARP per LOR; lane handles kz = lane + 32j, j=0..3.
template <int S0, int S1, bool TPOSE>
__global__ __launch_bounds__(32 * WARPS_PER_BLOCK, 6)
void tor_fast_kernel(const float* __restrict__ img_in, int set,
                     float* __restrict__ out, int n_lors)
{
    const float* img = TPOSE ? (const float*)g_imgT : img_in;

    const int warp = threadIdx.x >> 5;
    const int lane = threadIdx.x & 31;
    const int lor  = blockIdx.x * WARPS_PER_BLOCK + warp;
    if (lor >= n_lors) return;

    const float4 P = __ldg(&g_prm[set][lor]);

    const float KW2    = 2.8647889756541160f;   // 9/pi
    const float INV_KW = 0.59081795026046127f;  // 1/sqrt(9/pi)

    float accE = 0.0f, accO = 0.0f;   // parity-split accumulators

#pragma unroll
    for (int j = 0; j < 4; ++j) {
        const int   kz  = lane + 32 * j;
        const float kzf = (float)kz;
        const float fx = fmaf(kzf, P.y, P.x);
        const float fy = fmaf(kzf, P.w, P.z);
        const int ix = __float2int_rn(fx);   // half-to-even == jnp.round
        const int iy = __float2int_rn(fy);

        const float ux = (float)ix - fx;     // in [-0.5, 0.5]
        const float uy = (float)iy - fy;
        float xs[5], ys[5];
#pragma unroll
        for (int o = 0; o < 5; ++o) {
            const float a = ux + (float)(o - 2);
            const float b = uy + (float)(o - 2);
            xs[o] = a * a;
            ys[o] = b * b;
        }

        float t0 = 0.0f, t1 = 0.0f;        // per-group temporaries (2 chains)

        if ((unsigned)(ix - 2) <= (unsigned)(G - 5) &&
            (unsigned)(iy - 2) <= (unsigned)(G - 5)) {
            const float* p = img + ix * S0 + iy * S1 + kz;
#pragma unroll
            for (int o0 = -2; o0 <= 2; ++o0) {
#pragma unroll
                for (int o1 = -2; o1 <= 2; ++o1) {
                    const int r2 = o0 * o0 + o1 * o1;
                    if (r2 == 8) continue;               // corners: never pass
                    const float d2 = xs[o0 + 2] + ys[o1 + 2];
                    const bool even = (((o0 + o1) & 1) == 0);
                    if (r2 == 0) {
                        // center tap: always pass, d2 may be 0 -> guarded sqrt
                        const float w = fmaf(-fast_sqrt_guard(d2), INV_KW, 1.0f);
                        t0 = fmaf(w, __ldg(p), t0);
                    } else if (r2 <= 1) {
                        // other cross taps: always pass, d2 >= 0.25
                        const float w = fmaf(-fast_sqrt_nz(d2), INV_KW, 1.0f);
                        const float v = __ldg(p + (o0 * S0 + o1 * S1));
                        if (even) t0 = fmaf(w, v, t0); else t1 = fmaf(w, v, t1);
                    } else if (d2 < KW2) {
                        // ring taps: load only when weight positive (d2 >= 0.5)
                        const float w = fmaf(-fast_sqrt_nz(d2), INV_KW, 1.0f);
                        const float v = __ldg(p + (o0 * S0 + o1 * S1));
                        if (even) t0 = fmaf(w, v, t0); else t1 = fmaf(w, v, t1);
                    }
                }
            }
        } else {
            // edge fallback (not hit for this dataset): per-tap bounds
#pragma unroll
            for (int o0 = -2; o0 <= 2; ++o0) {
#pragma unroll
                for (int o1 = -2; o1 <= 2; ++o1) {
                    if (o0 * o0 + o1 * o1 == 8) continue;
                    const int jx = ix + o0;
                    const int jy = iy + o1;
                    const float d2 = xs[o0 + 2] + ys[o1 + 2];
                    if (d2 < KW2 && (unsigned)jx < (unsigned)G && (unsigned)jy < (unsigned)G) {
                        const float w = fmaf(-fast_sqrt_guard(d2), INV_KW, 1.0f);
                        t0 = fmaf(w, __ldg(img + jx * S0 + jy * S1 + kz), t0);
                    }
                }
            }
        }

        accE += t0;
        accO += t1;
    }

    float acc = accE + accO;

    // warp reduction
#pragma unroll
    for (int sft = 16; sft > 0; sft >>= 1)
        acc += __shfl_down_sync(0xFFFFFFFFu, acc, sft);
    if (lane == 0)
        out[lor] = acc * __ldg(&g_stp[set][lor]);
}

// ------------------------ generic fallback -----------------------------------
template <int P0, int P1, int P2>
__global__ __launch_bounds__(128)
void tor_generic_kernel(const float* __restrict__ img_in,
                        const int*   __restrict__ grid,
                        const float* __restrict__ center,
                        const float* __restrict__ size,
                        const float* __restrict__ lors,
                        float*       __restrict__ out,
                        int n_lors)
{
    const int lor = blockIdx.x;
    if (lor >= n_lors) return;
    const int g0 = grid[0], g1 = grid[1], g2 = grid[2];
    const int gs[3]   = { g0, g1, g2 };
    const int istr[3] = { g1 * g2, g2, 1 };
    const int n0 = gs[P0], n1 = gs[P1], n2 = gs[P2];
    const int s0 = istr[P0], s1 = istr[P1], s2 = istr[P2];
    const float* img = img_in;

    const float sz0 = size[P0], sz1 = size[P1], sz2 = size[P2];
    const float vs0 = sz0 / (float)n0, vs1 = sz1 / (float)n1, vs2 = sz2 / (float)n2;
    const float lo0 = center[P0] - sz0 * 0.5f;
    const float lo1 = center[P1] - sz1 * 0.5f;
    const float lo2 = center[P2] - sz2 * 0.5f;

    const float* L = lors + (size_t)lor * 6;
    const float p1x = __ldg(L + 0), p1y = __ldg(L + 1), p1z = __ldg(L + 2);
    const float dx = __ldg(L + 3) - p1x, dy = __ldg(L + 4) - p1y, dz = __ldg(L + 5) - p1z;
    const float len = sqrtf(dx * dx + dy * dy + dz * dz);
    const float step = vs2 * len / fabsf(dz);
    const float inv_dz = 1.0f / dz, inv_vs0 = 1.0f / vs0, inv_vs1 = 1.0f / vs1;
    const float KW2 = 2.8647889756541160f, INV_KW = 0.59081795026046127f;

    float acc = 0.0f;
    for (int kz = threadIdx.x; kz < n2; kz += blockDim.x) {
        const float zc = lo2 + ((float)kz + 0.5f) * vs2;
        const float t  = (zc - p1z) * inv_dz;
        const float fx = (fmaf(t, dx, p1x) - lo0) * inv_vs0 - 0.5f;
        const float fy = (fmaf(t, dy, p1y) - lo1) * inv_vs1 - 0.5f;
        const int ix = __float2int_rn(fx);
        const int iy = __float2int_rn(fy);
#pragma unroll
        for (int o0 = -2; o0 <= 2; ++o0) {
#pragma unroll
            for (int o1 = -2; o1 <= 2; ++o1) {
                if (o0 * o0 + o1 * o1 == 8) continue;
                const int jx = ix + o0, jy = iy + o1;
                const float ddx = (float)jx - fx, ddy = (float)jy - fy;
                const float d2 = ddx * ddx + ddy * ddy;
                if (d2 < KW2 && (unsigned)jx < (unsigned)n0 && (unsigned)jy < (unsigned)n1) {
                    const float s = d2 * rsqrtf(fmaxf(d2, 1e-30f));
                    const float w = fmaf(-s, INV_KW, 1.0f);
                    acc = fmaf(w, __ldg(&img[jx * s0 + jy * s1 + kz * s2]), acc);
                }
            }
        }
    }
#pragma unroll
    for (int sft = 16; sft > 0; sft >>= 1)
        acc += __shfl_down_sync(0xFFFFFFFFu, acc, sft);
    __shared__ float wsum[4];
    if ((threadIdx.x & 31) == 0) wsum[threadIdx.x >> 5] = acc;
    __syncthreads();
    if (threadIdx.x == 0)
        out[lor] = (wsum[0] + wsum[1] + wsum[2] + wsum[3]) * step;
}

extern "C" void kernel_launch(void* const* d_in, const int* in_sizes, int n_in,
                              void* d_out, int out_size)
{
    const float* image  = (const float*)d_in[0];
    const int*   grid   = (const int*)  d_in[1];
    const float* center = (const float*)d_in[2];
    const float* size   = (const float*)d_in[3];
    const float* xlors  = (const float*)d_in[4];
    const float* ylors  = (const float*)d_in[5];
    const float* zlors  = (const float*)d_in[6];
    float* out = (float*)d_out;

    const int nx = in_sizes[4] / 6;
    const int ny = in_sizes[5] / 6;
    const int nz = in_sizes[6] / 6;

    const long long nimg = in_sizes[0];
    const bool fast = (nimg == (long long)G * G * G) &&
                      nx <= MAX_LORS && ny <= MAX_LORS && nz <= MAX_LORS;

    if (fast) {
        const int PT = 256;
        const int W = WARPS_PER_BLOCK;

        // Launch order chosen so the 4th kernel launch (where ncu's capture
        // empirically lands) is the HOT pz kernel.
        // #1-3: prep z, x, y
        if (nz > 0) prep_kernel<0, 1, 2><<<(nz + PT - 1) / PT, PT>>>(grid, center, size, zlors, nz, 2);
        if (nx > 0) prep_kernel<2, 0, 1><<<(nx + PT - 1) / PT, PT>>>(grid, center, size, xlors, nx, 0);
        if (ny > 0) prep_kernel<1, 0, 2><<<(ny + PT - 1) / PT, PT>>>(grid, center, size, ylors, ny, 1);

        // #4: pz hot kernel (image[jx][jy][kz] -> S0=GSQ, S1=G) — PROFILED
        if (nz > 0) tor_fast_kernel<GSQ, G,   false><<<(nz + W - 1) / W, 32 * W>>>(image, 2, out + nx + ny, nz);

        // #5: transpose for px frame (walked image axis must be stride-1)
        {
            dim3 tb(32, 8), tg(G / 32, G / 32, G);
            transpose_bc_kernel<<<tg, tb>>>(image);
        }

        // #6: px (g_imgT[jy][jx][kz] -> S0=G, S1=GSQ, TPOSE)
        if (nx > 0) tor_fast_kernel<G,   GSQ, true ><<<(nx + W - 1) / W, 32 * W>>>(image, 0, out, nx);
        // #7: py (image[jy][jx][kz] -> S0=G, S1=GSQ)
        if (ny > 0) tor_fast_kernel<G,   GSQ, false><<<(ny + W - 1) / W, 32 * W>>>(image, 1, out + nx, ny);
    } else {
        if (nx > 0) tor_generic_kernel<2, 0, 1><<<nx, 128>>>(image, grid, center, size, xlors, out, nx);
        if (ny > 0) tor_generic_kernel<1, 0, 2><<<ny, 128>>>(image, grid, center, size, ylors, out + nx, ny);
        if (nz > 0) tor_generic_kernel<0, 1, 2><<<nz, 128>>>(image, grid, center, size, zlors, out + nx + ny, nz);
    }
}